// round 10
// baseline (speedup 1.0000x reference)
#include <cuda_runtime.h>

#define ED  256
#define NH  8
#define NP  8
#define D   32
#define EPSF 1e-5f
#define MAXB 8
#define NS  3   // independent query streams per thread

// Per-batch packed (offx-0.5, offy-0.5, aw, 0) per (head, point), plus ready flags.
__device__ float4 g_pack[MAXB * NH * NP];
__device__ volatile int g_flag[MAXB];   // zero-initialized; stays 1 across replays (benign)

// ---------------------------------------------------------------------------
// Fused kernel. 1-D grid, b = bid % bs so the bs producer blocks are bids
// 0..bs-1 (scheduled first -> no deadlock). Producers compute the per-batch
// offsets/weights pack; everyone then runs the gather + LayerNorm body.
// Each block processes 12 queries: warp-pair (slot) handles q0,q1,q2 =
// qblk*12+slot+{0,4,8} as three independent gather streams (12 LDG.128 in
// flight per warp). Warp covers 128 channels = 4 heads; lane = 4 channels.
// ---------------------------------------------------------------------------
__global__ __launch_bounds__(256, 3) void sca_fused_kernel(
    const float* __restrict__ query,   // [bs, ED]
    const float* __restrict__ feat,    // [bs, nq, NH, D]
    const float* __restrict__ ref2d,   // [bs, nq, 2]
    const float* __restrict__ W_off,
    const float* __restrict__ b_off,
    const float* __restrict__ W_attn,
    const float* __restrict__ b_attn,
    const float* __restrict__ ln_g,
    const float* __restrict__ ln_b,
    const int*   __restrict__ hp,
    const int*   __restrict__ wp,
    float* __restrict__ out,           // [bs, nq, ED]
    int nq, int bs)
{
    const int bid  = blockIdx.x;
    const int t    = threadIdx.x;
    const int b    = bid % bs;
    const int qblk = bid / bs;

    __shared__ float4 s_pack[NH * NP];
    __shared__ float  s_red[NS * 16];

    // ---------------- producer path: compute g_pack[b] ----------------
    if (bid < bs) {
        __shared__ float sq[ED];
        __shared__ float p_off[NH * NP * 2];
        __shared__ float p_aw[NH * NP];

        sq[t] = query[b * ED + t];
        __syncthreads();

        if (t < NH * NP * 2) {
            float acc = b_off[t];
            #pragma unroll 8
            for (int k = 0; k < ED; k++)
                acc = fmaf(sq[k], W_off[k * (NH * NP * 2) + t], acc);
            p_off[t] = fmaxf(acc, 0.0f);
        }
        if (t < NH * NP) {
            float acc = b_attn[t];
            #pragma unroll 8
            for (int k = 0; k < ED; k++)
                acc = fmaf(sq[k], W_attn[k * (NH * NP) + t], acc);
            p_aw[t] = fmaxf(acc, 0.0f);
        }
        __syncthreads();

        if (t < NH * NP) {
            const int g = t & ~(NP - 1);
            float m = -1e30f;
            #pragma unroll
            for (int i = 0; i < NP; i++) m = fmaxf(m, p_aw[g + i]);
            float s = 0.0f;
            #pragma unroll
            for (int i = 0; i < NP; i++) s += expf(p_aw[g + i] - m);
            const float aw = expf(p_aw[t] - m) / s;
            g_pack[b * NH * NP + t] = make_float4(p_off[2 * t] - 0.5f,
                                                  p_off[2 * t + 1] - 0.5f,
                                                  aw, 0.0f);
        }
        __syncthreads();
        __threadfence();                    // release g_pack writes
        if (t == 0) g_flag[b] = 1;
    } else {
        // ---------------- consumer path: wait for producer ----------------
        if (t == 0) {
            while (g_flag[b] == 0) { __nanosleep(64); }
            __threadfence();                // acquire
        }
    }
    __syncthreads();

    // ---------------- main body: NS independent queries per thread --------
    const int ww   = t >> 5;           // warp in block: 0..7
    const int lane = t & 31;
    const int slot = ww >> 1;          // query slot in block: 0..3
    const int half = ww & 1;           // which 128-channel half

    const int head = half * 4 + (lane >> 3);   // 0..7
    const int sub  = lane & 7;                 // 0..7
    const int ch   = head * D + sub * 4;       // channel base (multiple of 4)

    if (t < NH * NP) s_pack[t] = g_pack[b * NH * NP + t];
    __syncthreads();

    const int w = *wp;
    const int h = *hp;
    const float fw = (float)w;
    const float fh = (float)h;
    const int wrow = w << 10;          // bytes per image row (w * ED * 4)

    int    qs[NS];
    float2 rrs[NS];
    float4 accs[NS];
    #pragma unroll
    for (int s = 0; s < NS; s++) {
        qs[s]   = min(qblk * (4 * NS) + slot + 4 * s, nq - 1);
        rrs[s]  = __ldg((const float2*)(ref2d + ((long)b * nq + qs[s]) * 2));
        accs[s] = make_float4(0.f, 0.f, 0.f, 0.f);
    }

    // per-batch feature slab base for this (head, channel)
    const char* fbase = (const char*)(feat + ((long)b * nq) * ED + ch);

    #pragma unroll
    for (int p = 0; p < NP; p++) {
        const float4 pk = s_pack[head * NP + p];

        int   o00[NS];
        bool  v00[NS], v01[NS], v10[NS], v11[NS];
        float fxs[NS], fys[NS];

        #pragma unroll
        for (int s = 0; s < NS; s++) {
            const float x = fmaf(rrs[s].x, fw, pk.x);
            const float y = fmaf(rrs[s].y, fh, pk.y);
            const float x0f = floorf(x);
            const float y0f = floorf(y);
            fxs[s] = x - x0f;
            fys[s] = y - y0f;
            const int x0 = (int)x0f;
            const int y0 = (int)y0f;
            const bool vx0 = (unsigned)x0       < (unsigned)w;
            const bool vx1 = (unsigned)(x0 + 1) < (unsigned)w;
            const bool vy0 = (unsigned)y0       < (unsigned)h;
            const bool vy1 = (unsigned)(y0 + 1) < (unsigned)h;
            v00[s] = vy0 & vx0;  v01[s] = vy0 & vx1;
            v10[s] = vy1 & vx0;  v11[s] = vy1 & vx1;
            o00[s] = (y0 * w + x0) << 10;       // byte offset, 32-bit
        }

        // all 4*NS loads issued back-to-back (independent streams)
        const float4 z = make_float4(0.f, 0.f, 0.f, 0.f);
        float4 c00[NS], c01[NS], c10[NS], c11[NS];
        #pragma unroll
        for (int s = 0; s < NS; s++) {
            c00[s] = z; c01[s] = z; c10[s] = z; c11[s] = z;
            if (v00[s]) c00[s] = __ldg((const float4*)(fbase + o00[s]));
            if (v01[s]) c01[s] = __ldg((const float4*)(fbase + o00[s] + 1024));
            if (v10[s]) c10[s] = __ldg((const float4*)(fbase + o00[s] + wrow));
            if (v11[s]) c11[s] = __ldg((const float4*)(fbase + o00[s] + wrow + 1024));
        }

        #pragma unroll
        for (int s = 0; s < NS; s++) {
            const float omx = 1.0f - fxs[s];
            const float omy = 1.0f - fys[s];
            const float a0  = pk.z * omy;
            const float a1  = pk.z * fys[s];
            const float w00 = a0 * omx, w01 = a0 * fxs[s];
            const float w10 = a1 * omx, w11 = a1 * fxs[s];
            accs[s].x = fmaf(w00, c00[s].x, fmaf(w01, c01[s].x, fmaf(w10, c10[s].x, fmaf(w11, c11[s].x, accs[s].x))));
            accs[s].y = fmaf(w00, c00[s].y, fmaf(w01, c01[s].y, fmaf(w10, c10[s].y, fmaf(w11, c11[s].y, accs[s].y))));
            accs[s].z = fmaf(w00, c00[s].z, fmaf(w01, c01[s].z, fmaf(w10, c10[s].z, fmaf(w11, c11[s].z, accs[s].z))));
            accs[s].w = fmaf(w00, c00[s].w, fmaf(w01, c01[s].w, fmaf(w10, c10[s].w, fmaf(w11, c11[s].w, accs[s].w))));
        }
    }

    // residual with broadcast query (same for all streams)
    const float4 qv = __ldg((const float4*)(query + b * ED + ch));
    float4 res[NS];
    #pragma unroll
    for (int s = 0; s < NS; s++) {
        res[s].x = accs[s].x + qv.x;
        res[s].y = accs[s].y + qv.y;
        res[s].z = accs[s].z + qv.z;
        res[s].w = accs[s].w + qv.w;
    }

    // LayerNorm over ED=256 (2 warps per query, all streams)
    float sm[NS], s2[NS];
    #pragma unroll
    for (int s = 0; s < NS; s++) {
        sm[s] = res[s].x + res[s].y + res[s].z + res[s].w;
        s2[s] = res[s].x * res[s].x + res[s].y * res[s].y
              + res[s].z * res[s].z + res[s].w * res[s].w;
    }
    #pragma unroll
    for (int o = 16; o; o >>= 1) {
        #pragma unroll
        for (int s = 0; s < NS; s++) {
            sm[s] += __shfl_xor_sync(0xFFFFFFFFu, sm[s], o);
            s2[s] += __shfl_xor_sync(0xFFFFFFFFu, s2[s], o);
        }
    }
    if (lane == 0) {
        #pragma unroll
        for (int s = 0; s < NS; s++) {
            s_red[s * 16 + ww]     = sm[s];
            s_red[s * 16 + 8 + ww] = s2[s];
        }
    }
    __syncthreads();

    const float4 gg = __ldg((const float4*)(ln_g + ch));
    const float4 bb = __ldg((const float4*)(ln_b + ch));

    #pragma unroll
    for (int s = 0; s < NS; s++) {
        const float S   = s_red[s * 16 + slot * 2]     + s_red[s * 16 + slot * 2 + 1];
        const float S2  = s_red[s * 16 + 8 + slot * 2] + s_red[s * 16 + 8 + slot * 2 + 1];
        const float mu  = S * (1.0f / ED);
        const float var = S2 * (1.0f / ED) - mu * mu;
        const float inv = rsqrtf(var + EPSF);
        float4 o4;
        o4.x = (res[s].x - mu) * inv * gg.x + bb.x;
        o4.y = (res[s].y - mu) * inv * gg.y + bb.y;
        o4.z = (res[s].z - mu) * inv * gg.z + bb.z;
        o4.w = (res[s].w - mu) * inv * gg.w + bb.w;
        *(float4*)(out + (((long)b * nq) + qs[s]) * ED + ch) = o4;
    }
}

// ---------------------------------------------------------------------------
extern "C" void kernel_launch(void* const* d_in, const int* in_sizes, int n_in,
                              void* d_out, int out_size) {
    const float* query  = (const float*)d_in[0];
    const float* feat   = (const float*)d_in[1];
    const float* ref2d  = (const float*)d_in[2];
    const float* W_off  = (const float*)d_in[3];
    const float* b_off  = (const float*)d_in[4];
    const float* W_attn = (const float*)d_in[5];
    const float* b_attn = (const float*)d_in[6];
    const float* ln_g   = (const float*)d_in[7];
    const float* ln_b   = (const float*)d_in[8];
    const int*   hp     = (const int*)d_in[9];
    const int*   wp     = (const int*)d_in[10];
    float* out = (float*)d_out;

    const int bs = in_sizes[0] / ED;           // 8
    const int nq = in_sizes[2] / (bs * 2);     // h*w = 4096

    const int qblocks = (nq + 4 * NS - 1) / (4 * NS);
    sca_fused_kernel<<<qblocks * bs, 256>>>(query, feat, ref2d,
                                            W_off, b_off, W_attn, b_attn,
                                            ln_g, ln_b, hp, wp, out, nq, bs);
}